// round 4
// baseline (speedup 1.0000x reference)
#include <cuda_runtime.h>
#include <cuda_bf16.h>

#define N_NODES 20000
#define N_EDGES 640000
#define HIDDEN  128
#define KDIM    256   // concat [agg | x]

// ---------------- scratch (device globals; 16B-aligned for float4) ---------
__device__ __align__(16) float g_summed[N_NODES * HIDDEN];   // 10.24 MB
__device__ __align__(16) float g_cnt[N_NODES];
__device__ __align__(16) float g_rcnt[N_NODES];
__device__ __align__(16) float g_Wt[KDIM * HIDDEN];          // Wt[k][j]
__device__ int g_is64;

// ---------------- kernel 0: detect edge_index dtype ------------------------
// int64 node ids < 20000 => every odd 32-bit word is zero. For int32 layout
// the odd words are random node ids; P(128 consecutive all zero) ~ 0.
__global__ void detect_kernel(const int* __restrict__ ei_raw) {
    if (blockIdx.x == 0 && threadIdx.x == 0) {
        int ok64 = 1;
#pragma unroll 1
        for (int i = 1; i < 256; i += 2) ok64 &= (ei_raw[i] == 0);
        g_is64 = ok64;
    }
}

// ---------------- kernel 1: zero accumulators + build Wt -------------------
// launched with exactly N_NODES*HIDDEN/4 = 640000 threads
__global__ void init_kernel(const float* __restrict__ Wl,
                            const float* __restrict__ Wr) {
    int i = blockIdx.x * blockDim.x + threadIdx.x;
    reinterpret_cast<float4*>(g_summed)[i] = make_float4(0.f, 0.f, 0.f, 0.f);
    if (i < N_NODES) g_cnt[i] = 0.0f;
    if (i < KDIM * HIDDEN) {
        int k = i >> 7;        // /128
        int j = i & 127;
        g_Wt[i] = (k < HIDDEN) ? Wl[j * HIDDEN + k]
                               : Wr[j * HIDDEN + (k - HIDDEN)];
    }
}

// ---------------- kernel 2: edge scatter (1 warp per edge) -----------------
__global__ void scatter_kernel(const float* __restrict__ feat,
                               const void* __restrict__ ei) {
    int gtid = blockIdx.x * blockDim.x + threadIdx.x;
    int e    = gtid >> 5;
    int lane = gtid & 31;
    if (e >= N_EDGES) return;

    int s, d;
    if (g_is64) {
        const long long* p64 = (const long long*)ei;
        s = (int)p64[e];
        d = (int)p64[N_EDGES + e];
    } else {
        const int* p32 = (const int*)ei;
        s = p32[e];
        d = p32[N_EDGES + e];
    }
    // defensive: never form a wild address
    if ((unsigned)s >= N_NODES || (unsigned)d >= N_NODES) return;

    float4 v = *reinterpret_cast<const float4*>(&feat[s * HIDDEN + lane * 4]);
    float* p = &g_summed[d * HIDDEN + lane * 4];
    atomicAdd(p + 0, v.x);   // REDG.ADD.F32 (no return)
    atomicAdd(p + 1, v.y);
    atomicAdd(p + 2, v.z);
    atomicAdd(p + 3, v.w);
    if (lane == 0) atomicAdd(&g_cnt[d], 1.0f);
}

// ---------------- kernel 3: reciprocal counts ------------------------------
__global__ void rcnt_kernel() {
    int i = blockIdx.x * blockDim.x + threadIdx.x;
    if (i < N_NODES) g_rcnt[i] = 1.0f / fmaxf(g_cnt[i], 1.0f);
}

// ---------------- kernel 4: fused SGEMM ------------------------------------
// out[m][j] = sum_k A[m][k] * Wt[k][j] + b[j]
//   A[m][k] = k<128 ? summed[m][k]*rcnt[m] : feat[m][k-128]
#define BM 128
#define BN 128
#define BK 32
#define TM 8
#define TN 8

__global__ __launch_bounds__(256)
void gemm_kernel(const float* __restrict__ feat,
                 const float* __restrict__ bias,
                 float* __restrict__ out) {
    __shared__ float As[BM][BK];   // 16 KB
    __shared__ float Bs[BK][BN];   // 16 KB

    const int tid     = threadIdx.x;
    const int block_m = blockIdx.x * BM;
    const int trow    = tid / 16;  // 0..15
    const int tcol    = tid % 16;  // 0..15

    float acc[TM][TN];
#pragma unroll
    for (int i = 0; i < TM; i++)
#pragma unroll
        for (int j = 0; j < TN; j++) acc[i][j] = 0.0f;

    float bfrag[TN];
#pragma unroll
    for (int j = 0; j < TN; j++) bfrag[j] = __ldg(&bias[tcol * TN + j]);

    for (int k0 = 0; k0 < KDIM; k0 += BK) {
        const bool from_summed = (k0 < HIDDEN);
        // --- load A tile: 128 rows x 32 cols = 1024 float4, 256 thr x 4 ---
#pragma unroll
        for (int it = 0; it < 4; it++) {
            int slot = tid + it * 256;
            int r    = slot >> 3;        // 0..127
            int c4   = slot & 7;         // float4 index within 32 cols
            int m    = block_m + r;
            float4 v = make_float4(0.f, 0.f, 0.f, 0.f);
            if (m < N_NODES) {
                if (from_summed) {
                    v = *reinterpret_cast<const float4*>(
                            &g_summed[m * HIDDEN + k0 + c4 * 4]);
                    float rc = g_rcnt[m];
                    v.x *= rc; v.y *= rc; v.z *= rc; v.w *= rc;
                } else {
                    v = *reinterpret_cast<const float4*>(
                            &feat[m * HIDDEN + (k0 - HIDDEN) + c4 * 4]);
                }
            }
            *reinterpret_cast<float4*>(&As[r][c4 * 4]) = v;
        }
        // --- load B tile: 32 x 128 = 1024 float4, 256 thr x 4 ---
#pragma unroll
        for (int it = 0; it < 4; it++) {
            int slot = tid + it * 256;
            int kk   = slot >> 5;        // 0..31
            int j4   = slot & 31;
            *reinterpret_cast<float4*>(&Bs[kk][j4 * 4]) =
                *reinterpret_cast<const float4*>(&g_Wt[(k0 + kk) * HIDDEN + j4 * 4]);
        }
        __syncthreads();

#pragma unroll
        for (int kk = 0; kk < BK; kk++) {
            float a_frag[TM];
#pragma unroll
            for (int i = 0; i < TM; i++) a_frag[i] = As[trow * TM + i][kk];
            float4 b0 = *reinterpret_cast<const float4*>(&Bs[kk][tcol * TN]);
            float4 b1 = *reinterpret_cast<const float4*>(&Bs[kk][tcol * TN + 4]);
            float b_frag[TN] = {b0.x, b0.y, b0.z, b0.w, b1.x, b1.y, b1.z, b1.w};
#pragma unroll
            for (int i = 0; i < TM; i++)
#pragma unroll
                for (int j = 0; j < TN; j++)
                    acc[i][j] += a_frag[i] * b_frag[j];
        }
        __syncthreads();
    }

#pragma unroll
    for (int i = 0; i < TM; i++) {
        int m = block_m + trow * TM + i;
        if (m < N_NODES) {
            float4 o0, o1;
            o0.x = acc[i][0] + bfrag[0];
            o0.y = acc[i][1] + bfrag[1];
            o0.z = acc[i][2] + bfrag[2];
            o0.w = acc[i][3] + bfrag[3];
            o1.x = acc[i][4] + bfrag[4];
            o1.y = acc[i][5] + bfrag[5];
            o1.z = acc[i][6] + bfrag[6];
            o1.w = acc[i][7] + bfrag[7];
            *reinterpret_cast<float4*>(&out[m * HIDDEN + tcol * TN])     = o0;
            *reinterpret_cast<float4*>(&out[m * HIDDEN + tcol * TN + 4]) = o1;
        }
    }
}

// ---------------- launcher --------------------------------------------------
extern "C" void kernel_launch(void* const* d_in, const int* in_sizes, int n_in,
                              void* d_out, int out_size) {
    // Resolve inputs by unique element counts (robust to metadata ordering):
    //   features   : 2,560,000   edge_index : 1,280,000
    //   W_l, W_r   : 16,384 each (relative order kept)   b_l : 128
    const float* feat = nullptr;
    const void*  ei   = nullptr;
    const float* Wl   = nullptr;
    const float* bl   = nullptr;
    const float* Wr   = nullptr;
    for (int i = 0; i < n_in; i++) {
        int sz = in_sizes[i];
        if (sz == N_NODES * HIDDEN)      feat = (const float*)d_in[i];
        else if (sz == 2 * N_EDGES)      ei   = d_in[i];
        else if (sz == HIDDEN * HIDDEN) { if (!Wl) Wl = (const float*)d_in[i];
                                          else     Wr = (const float*)d_in[i]; }
        else if (sz == HIDDEN)           bl   = (const float*)d_in[i];
    }
    float* out = (float*)d_out;

    detect_kernel<<<1, 32>>>((const int*)ei);

    init_kernel<<<(N_NODES * HIDDEN / 4 + 255) / 256, 256>>>(Wl, Wr);

    {
        long long total_threads = (long long)N_EDGES * 32;
        int blocks = (int)((total_threads + 255) / 256);
        scatter_kernel<<<blocks, 256>>>(feat, ei);
    }

    rcnt_kernel<<<(N_NODES + 255) / 256, 256>>>();

    gemm_kernel<<<(N_NODES + BM - 1) / BM, 256>>>(feat, bl, out);
}

// round 6
// speedup vs baseline: 1.8020x; 1.8020x over previous
#include <cuda_runtime.h>
#include <cuda_bf16.h>

#define N_NODES 20000
#define N_EDGES 640000
#define HIDDEN  128
#define KDIM    256   // concat [agg | x]

// ---------------- scratch (device globals; 16B-aligned) --------------------
__device__ __align__(16) float g_agg[N_NODES * HIDDEN];      // mean-aggregated
__device__ __align__(16) float g_Wt[KDIM * HIDDEN];          // Wt[k][j]
__device__ int g_cnt[N_NODES];        // histogram counters
__device__ int g_rowstart[N_NODES + 1];
__device__ int g_wofs[N_NODES];       // running write offsets
__device__ int g_srcidx[N_EDGES];     // CSR src list
__device__ int g_is64;

// ---------------- kernel 0: detect edge_index dtype ------------------------
__global__ void detect_kernel(const int* __restrict__ ei_raw) {
    if (blockIdx.x == 0 && threadIdx.x == 0) {
        int ok64 = 1;
#pragma unroll 1
        for (int i = 1; i < 256; i += 2) ok64 &= (ei_raw[i] == 0);
        g_is64 = ok64;
    }
}

__device__ __forceinline__ int load_idx(const void* ei, int pos) {
    if (g_is64) return (int)((const long long*)ei)[pos];
    return ((const int*)ei)[pos];
}

// ---------------- kernel 1: build Wt + zero counters -----------------------
// grid covers KDIM*HIDDEN = 32768 threads
__global__ void init_kernel(const float* __restrict__ Wl,
                            const float* __restrict__ Wr) {
    int i = blockIdx.x * blockDim.x + threadIdx.x;
    if (i < KDIM * HIDDEN) {
        int k = i >> 7;        // /128
        int j = i & 127;
        g_Wt[i] = (k < HIDDEN) ? Wl[j * HIDDEN + k]
                               : Wr[j * HIDDEN + (k - HIDDEN)];
    }
    if (i < N_NODES) g_cnt[i] = 0;
}

// ---------------- kernel 2: histogram of dst ------------------------------
__global__ void hist_kernel(const void* __restrict__ ei) {
    int e = blockIdx.x * blockDim.x + threadIdx.x;
    if (e >= N_EDGES) return;
    int d = load_idx(ei, N_EDGES + e);
    if ((unsigned)d < N_NODES) atomicAdd(&g_cnt[d], 1);
}

// ---------------- kernel 3: exclusive prefix scan (single block) -----------
#define SCAN_T 1024
__global__ __launch_bounds__(SCAN_T)
void scan_kernel() {
    __shared__ int partial[SCAN_T];
    const int PER = (N_NODES + SCAN_T - 1) / SCAN_T;   // 20
    int t = threadIdx.x;
    int base = t * PER;
    int sum = 0;
#pragma unroll 1
    for (int i = 0; i < PER; i++) {
        int idx = base + i;
        if (idx < N_NODES) sum += g_cnt[idx];
    }
    partial[t] = sum;
    __syncthreads();
    // Hillis-Steele inclusive scan
    for (int off = 1; off < SCAN_T; off <<= 1) {
        int v = partial[t];
        int add = (t >= off) ? partial[t - off] : 0;
        __syncthreads();
        partial[t] = v + add;
        __syncthreads();
    }
    int run = (t > 0) ? partial[t - 1] : 0;   // exclusive offset
#pragma unroll 1
    for (int i = 0; i < PER; i++) {
        int idx = base + i;
        if (idx < N_NODES) {
            g_rowstart[idx] = run;
            g_wofs[idx]     = run;
            run += g_cnt[idx];
        }
    }
    if (t == SCAN_T - 1) g_rowstart[N_NODES] = run;
}

// ---------------- kernel 4: place src into CSR -----------------------------
__global__ void place_kernel(const void* __restrict__ ei) {
    int e = blockIdx.x * blockDim.x + threadIdx.x;
    if (e >= N_EDGES) return;
    int s = load_idx(ei, e);
    int d = load_idx(ei, N_EDGES + e);
    if ((unsigned)s >= N_NODES || (unsigned)d >= N_NODES) return;
    int pos = atomicAdd(&g_wofs[d], 1);
    g_srcidx[pos] = s;
}

// ---------------- kernel 5: atomic-free gather + mean ----------------------
// one warp per dst node; each lane owns 4 consecutive feature columns
__global__ void gather_kernel(const float* __restrict__ feat) {
    int gtid = blockIdx.x * blockDim.x + threadIdx.x;
    int nid  = gtid >> 5;
    int lane = gtid & 31;
    if (nid >= N_NODES) return;

    int beg = g_rowstart[nid];
    int end = g_rowstart[nid + 1];

    float4 acc = make_float4(0.f, 0.f, 0.f, 0.f);
    int i = beg;
#pragma unroll 1
    for (; i + 4 <= end; i += 4) {
        int s0 = g_srcidx[i + 0];
        int s1 = g_srcidx[i + 1];
        int s2 = g_srcidx[i + 2];
        int s3 = g_srcidx[i + 3];
        float4 v0 = *reinterpret_cast<const float4*>(&feat[s0 * HIDDEN + lane * 4]);
        float4 v1 = *reinterpret_cast<const float4*>(&feat[s1 * HIDDEN + lane * 4]);
        float4 v2 = *reinterpret_cast<const float4*>(&feat[s2 * HIDDEN + lane * 4]);
        float4 v3 = *reinterpret_cast<const float4*>(&feat[s3 * HIDDEN + lane * 4]);
        acc.x += v0.x + v1.x + v2.x + v3.x;
        acc.y += v0.y + v1.y + v2.y + v3.y;
        acc.z += v0.z + v1.z + v2.z + v3.z;
        acc.w += v0.w + v1.w + v2.w + v3.w;
    }
#pragma unroll 1
    for (; i < end; i++) {
        int s = g_srcidx[i];
        float4 v = *reinterpret_cast<const float4*>(&feat[s * HIDDEN + lane * 4]);
        acc.x += v.x; acc.y += v.y; acc.z += v.z; acc.w += v.w;
    }
    int deg = end - beg;
    float inv = 1.0f / (float)max(deg, 1);
    acc.x *= inv; acc.y *= inv; acc.z *= inv; acc.w *= inv;
    *reinterpret_cast<float4*>(&g_agg[nid * HIDDEN + lane * 4]) = acc;
}

// ---------------- kernel 6: fused SGEMM ------------------------------------
// out[m][j] = sum_k A[m][k] * Wt[k][j] + b[j],  A = [agg | feat]
#define BM 128
#define BN 128
#define BK 32
#define TM 8
#define TN 8

__global__ __launch_bounds__(256)
void gemm_kernel(const float* __restrict__ feat,
                 const float* __restrict__ bias,
                 float* __restrict__ out) {
    __shared__ float As[BM][BK];
    __shared__ float Bs[BK][BN];

    const int tid     = threadIdx.x;
    const int block_m = blockIdx.x * BM;
    const int trow    = tid / 16;
    const int tcol    = tid % 16;

    float acc[TM][TN];
#pragma unroll
    for (int i = 0; i < TM; i++)
#pragma unroll
        for (int j = 0; j < TN; j++) acc[i][j] = 0.0f;

    float bfrag[TN];
#pragma unroll
    for (int j = 0; j < TN; j++) bfrag[j] = __ldg(&bias[tcol * TN + j]);

    for (int k0 = 0; k0 < KDIM; k0 += BK) {
        const bool from_agg = (k0 < HIDDEN);
#pragma unroll
        for (int it = 0; it < 4; it++) {
            int slot = tid + it * 256;
            int r    = slot >> 3;
            int c4   = slot & 7;
            int m    = block_m + r;
            float4 v = make_float4(0.f, 0.f, 0.f, 0.f);
            if (m < N_NODES) {
                v = from_agg
                  ? *reinterpret_cast<const float4*>(&g_agg[m * HIDDEN + k0 + c4 * 4])
                  : *reinterpret_cast<const float4*>(&feat[m * HIDDEN + (k0 - HIDDEN) + c4 * 4]);
            }
            *reinterpret_cast<float4*>(&As[r][c4 * 4]) = v;
        }
#pragma unroll
        for (int it = 0; it < 4; it++) {
            int slot = tid + it * 256;
            int kk   = slot >> 5;
            int j4   = slot & 31;
            *reinterpret_cast<float4*>(&Bs[kk][j4 * 4]) =
                *reinterpret_cast<const float4*>(&g_Wt[(k0 + kk) * HIDDEN + j4 * 4]);
        }
        __syncthreads();

#pragma unroll
        for (int kk = 0; kk < BK; kk++) {
            float a_frag[TM];
#pragma unroll
            for (int i = 0; i < TM; i++) a_frag[i] = As[trow * TM + i][kk];
            float4 b0 = *reinterpret_cast<const float4*>(&Bs[kk][tcol * TN]);
            float4 b1 = *reinterpret_cast<const float4*>(&Bs[kk][tcol * TN + 4]);
            float b_frag[TN] = {b0.x, b0.y, b0.z, b0.w, b1.x, b1.y, b1.z, b1.w};
#pragma unroll
            for (int i = 0; i < TM; i++)
#pragma unroll
                for (int j = 0; j < TN; j++)
                    acc[i][j] += a_frag[i] * b_frag[j];
        }
        __syncthreads();
    }

#pragma unroll
    for (int i = 0; i < TM; i++) {
        int m = block_m + trow * TM + i;
        if (m < N_NODES) {
            float4 o0, o1;
            o0.x = acc[i][0] + bfrag[0];
            o0.y = acc[i][1] + bfrag[1];
            o0.z = acc[i][2] + bfrag[2];
            o0.w = acc[i][3] + bfrag[3];
            o1.x = acc[i][4] + bfrag[4];
            o1.y = acc[i][5] + bfrag[5];
            o1.z = acc[i][6] + bfrag[6];
            o1.w = acc[i][7] + bfrag[7];
            *reinterpret_cast<float4*>(&out[m * HIDDEN + tcol * TN])     = o0;
            *reinterpret_cast<float4*>(&out[m * HIDDEN + tcol * TN + 4]) = o1;
        }
    }
}

// ---------------- launcher --------------------------------------------------
extern "C" void kernel_launch(void* const* d_in, const int* in_sizes, int n_in,
                              void* d_out, int out_size) {
    const float* feat = nullptr;
    const void*  ei   = nullptr;
    const float* Wl   = nullptr;
    const float* bl   = nullptr;
    const float* Wr   = nullptr;
    for (int i = 0; i < n_in; i++) {
        int sz = in_sizes[i];
        if (sz == N_NODES * HIDDEN)      feat = (const float*)d_in[i];
        else if (sz == 2 * N_EDGES)      ei   = d_in[i];
        else if (sz == HIDDEN * HIDDEN) { if (!Wl) Wl = (const float*)d_in[i];
                                          else     Wr = (const float*)d_in[i]; }
        else if (sz == HIDDEN)           bl   = (const float*)d_in[i];
    }
    float* out = (float*)d_out;

    detect_kernel<<<1, 32>>>((const int*)ei);
    init_kernel<<<(KDIM * HIDDEN + 255) / 256, 256>>>(Wl, Wr);
    hist_kernel<<<(N_EDGES + 255) / 256, 256>>>(ei);
    scan_kernel<<<1, SCAN_T>>>();
    place_kernel<<<(N_EDGES + 255) / 256, 256>>>(ei);
    gather_kernel<<<(N_NODES * 32 + 255) / 256, 256>>>(feat);
    gemm_kernel<<<(N_NODES + BM - 1) / BM, 256>>>(feat, bl, out);
}